// round 1
// baseline (speedup 1.0000x reference)
#include <cuda_runtime.h>
#include <cstdint>

// ---------------------------------------------------------------------------
// GroundingNet: B=16, N=64, E=512
//   node path : x(1024,512) -> bn+relu(.@w1) -> bn+relu(.@w2) -> relu(.@w3)
//               -> sigmoid(.@wn)  => node_c (B,N,8)
//   see/mask  : scatter of edge list into per-node neighbor table
//   edge path : e1 = relu(Ai[i]+Aj[j]) (layer-1 decomposed), e2 = relu(e1@we2),
//               rel = sigmoid(e2@wei)  => rel (B,N,N,8)
//   outputs   : node_concepts (B*N,N,8) then edge_concepts (B*N,N,N,8),
//               concatenated flat in d_out (34,078,720 floats).
// ---------------------------------------------------------------------------

#define DINL __device__ __forceinline__

constexpr int Bb   = 16;
constexpr int Nn   = 64;
constexpr int Ee   = 512;
constexpr int CIMG = 512;
constexpr int H1c  = 256;
constexpr int H2c  = 128;
constexpr int H3c  = 64;
constexpr int Uu   = 8;
constexpr int Rr   = 8;
constexpr int EH   = 64;
constexpr int ROWS = Bb * Nn;            // 1024
constexpr int NODE_OUT = ROWS * Nn * Uu; // 524288

// ------------------------- scratch (device globals) ------------------------
__device__ float g_h1[ROWS * H1c];
__device__ float g_h2[ROWS * H2c];
__device__ float g_node[ROWS * Uu];
__device__ float g_Ai[ROWS * EH];
__device__ float g_AjT[Bb * EH * Nn];          // [b][c][n] transposed for coalesced gather
__device__ float g_rel[Bb * Nn * Nn * Rr];     // 2 MB, L2-resident
__device__ int   g_see[Bb * Nn * Nn];
__device__ int   g_cnt[Bb * Nn];

// packed fp32x2 FMA (sm_100+): 2 scalar FMAs per issued instruction
DINL float2 ffma2(float2 a, float2 b, float2 c) {
    float2 d;
    asm("fma.rn.f32x2 %0, %1, %2, %3;"
        : "=l"(reinterpret_cast<unsigned long long&>(d))
        : "l"(reinterpret_cast<unsigned long long&>(a)),
          "l"(reinterpret_cast<unsigned long long&>(b)),
          "l"(reinterpret_cast<unsigned long long&>(c)));
    return d;
}

// ---------------------------------------------------------------------------
// K1: build see / count.  One block per batch, 512 threads.
// pos[e] = 1 + #{e' < e : dst[e']==dst[e]};  see[b][n][0]=n, rest scatter (drop p>=N)
// ---------------------------------------------------------------------------
__global__ void __launch_bounds__(512) k_build_see(const int* __restrict__ edge_index) {
    const int b = blockIdx.x;
    const int t = threadIdx.x;
    __shared__ int ssrc[Ee];
    __shared__ int sdst[Ee];
    const int* ei = edge_index + (size_t)b * 2 * Ee;
    for (int e = t; e < Ee; e += 512) { ssrc[e] = ei[e]; sdst[e] = ei[Ee + e]; }
    for (int i = t; i < Nn * Nn; i += 512)
        g_see[b * Nn * Nn + i] = ((i & (Nn - 1)) == 0) ? (i >> 6) : 0;
    __syncthreads();
    // degree / count
    if (t < Nn) {
        int d = 0;
        #pragma unroll 8
        for (int e = 0; e < Ee; e++) d += (sdst[e] == t);
        g_cnt[b * Nn + t] = min(d + 1, Nn);
    }
    // scatter (indices unique: running position per dst)
    {
        const int e = t;       // 512 threads == E
        const int dst = sdst[e];
        int p = 1;
        for (int e2 = 0; e2 < e; e2++) p += (sdst[e2] == dst);
        if (p < Nn) g_see[b * Nn * Nn + dst * Nn + p] = ssrc[e];
    }
}

// ---------------------------------------------------------------------------
// K2: generic MLP layer, 32 rows x 64 cols per block, bn+relu epilogue.
// SEL==0: X=param (roi) -> g_h1 ;  SEL==1: X=g_h1 -> g_h2
// ---------------------------------------------------------------------------
template <int K, int CN, int SEL>
__global__ void __launch_bounds__(256) k_mlp(
    const float* __restrict__ Xin,
    const float* __restrict__ W,  const float* __restrict__ bias,
    const float* __restrict__ bng, const float* __restrict__ bnb,
    const float* __restrict__ bnm, const float* __restrict__ bnv) {
    constexpr int KC = 64;
    const float* X = (SEL == 0) ? Xin : g_h1;
    float* Y       = (SEL == 0) ? g_h1 : g_h2;
    const int r0 = blockIdx.x * 32;
    const int c0 = blockIdx.y * 64;
    const int t  = threadIdx.x;
    const int cc = t & 63;
    const int c  = c0 + cc;
    const int pg = t >> 6;          // 0..3 -> rows pg*8 .. pg*8+7
    __shared__ alignas(16) float xs[KC * 32];   // [k][row] transposed
    __shared__ alignas(16) float ws[KC * 64];   // [k][col]
    float2 acc[4] = {{0.f,0.f},{0.f,0.f},{0.f,0.f},{0.f,0.f}};

    for (int kc = 0; kc < K; kc += KC) {
        // stage X chunk (32 rows x 64 k), transposed into xs[k][r]
        for (int i = t; i < 512; i += 256) {
            const int r  = i >> 4;
            const int k4 = (i & 15) << 2;
            float4 xv = *(const float4*)&X[(size_t)(r0 + r) * K + kc + k4];
            xs[(k4 + 0) * 32 + r] = xv.x;
            xs[(k4 + 1) * 32 + r] = xv.y;
            xs[(k4 + 2) * 32 + r] = xv.z;
            xs[(k4 + 3) * 32 + r] = xv.w;
        }
        // stage W chunk (64 k x 64 cols)
        for (int i = t; i < KC * 16; i += 256) {
            const int k  = i >> 4;
            const int c4 = (i & 15) << 2;
            *(float4*)&ws[k * 64 + c4] =
                *(const float4*)&W[(size_t)(kc + k) * CN + c0 + c4];
        }
        __syncthreads();
        #pragma unroll
        for (int k = 0; k < KC; k++) {
            const float w = ws[k * 64 + cc];
            const float2 w2 = make_float2(w, w);
            #pragma unroll
            for (int q = 0; q < 4; q++) {
                float2 a = *(const float2*)&xs[k * 32 + pg * 8 + q * 2];
                acc[q] = ffma2(a, w2, acc[q]);
            }
        }
        __syncthreads();
    }
    // fused batchnorm + relu epilogue
    const float s  = bng[c] * rsqrtf(bnv[c] + 1e-5f);
    const float sh = bnb[c] - bnm[c] * s;
    const float bc = bias[c];
    #pragma unroll
    for (int q = 0; q < 4; q++) {
        const int row = pg * 8 + q * 2;
        Y[(size_t)(r0 + row    ) * CN + c] = fmaxf((acc[q].x + bc) * s + sh, 0.f);
        Y[(size_t)(r0 + row + 1) * CN + c] = fmaxf((acc[q].y + bc) * s + sh, 0.f);
    }
}

// ---------------------------------------------------------------------------
// K3: layer3 (128->64, relu) fused with node head (64->8, sigmoid).
// 32 rows per block (covers all 64 cols), 32 blocks.
// ---------------------------------------------------------------------------
__global__ void __launch_bounds__(256) k_mlp3(
    const float* __restrict__ w3, const float* __restrict__ b3,
    const float* __restrict__ wn, const float* __restrict__ bnc) {
    constexpr int K = 128, CN = 64, KC = 64;
    const int r0 = blockIdx.x * 32;
    const int t  = threadIdx.x;
    const int cc = t & 63;
    const int pg = t >> 6;
    __shared__ alignas(16) float xs[KC * 32];
    __shared__ alignas(16) float ws[KC * 64];
    __shared__ float h3s[32 * 65];
    __shared__ float wns[64 * 8];
    __shared__ float bncs[8];
    if (t < 8) bncs[t] = bnc[t];
    for (int i = t; i < 512; i += 256) wns[i] = wn[i];

    float2 acc[4] = {{0.f,0.f},{0.f,0.f},{0.f,0.f},{0.f,0.f}};
    for (int kc = 0; kc < K; kc += KC) {
        for (int i = t; i < 512; i += 256) {
            const int r  = i >> 4;
            const int k4 = (i & 15) << 2;
            float4 xv = *(const float4*)&g_h2[(size_t)(r0 + r) * K + kc + k4];
            xs[(k4 + 0) * 32 + r] = xv.x;
            xs[(k4 + 1) * 32 + r] = xv.y;
            xs[(k4 + 2) * 32 + r] = xv.z;
            xs[(k4 + 3) * 32 + r] = xv.w;
        }
        for (int i = t; i < KC * 16; i += 256) {
            const int k  = i >> 4;
            const int c4 = (i & 15) << 2;
            *(float4*)&ws[k * 64 + c4] =
                *(const float4*)&w3[(size_t)(kc + k) * CN + c4];
        }
        __syncthreads();
        #pragma unroll
        for (int k = 0; k < KC; k++) {
            const float w = ws[k * 64 + cc];
            const float2 w2 = make_float2(w, w);
            #pragma unroll
            for (int q = 0; q < 4; q++) {
                float2 a = *(const float2*)&xs[k * 32 + pg * 8 + q * 2];
                acc[q] = ffma2(a, w2, acc[q]);
            }
        }
        __syncthreads();
    }
    const float bc = b3[cc];
    #pragma unroll
    for (int q = 0; q < 4; q++) {
        const int row = pg * 8 + q * 2;
        h3s[(row    ) * 65 + cc] = fmaxf(acc[q].x + bc, 0.f);
        h3s[(row + 1) * 65 + cc] = fmaxf(acc[q].y + bc, 0.f);
    }
    __syncthreads();
    // node head: 32 rows x 8 outputs
    const int row = t >> 3, u = t & 7;
    float a = bncs[u];
    #pragma unroll
    for (int k = 0; k < 64; k++) a += h3s[row * 65 + k] * wns[k * 8 + u];
    g_node[(size_t)(r0 + row) * 8 + u] = 1.f / (1.f + __expf(-a));
}

// ---------------------------------------------------------------------------
// K4: edge layer-1 decomposition.  Ai = attr@we1[:9]+be1, AjT = (attr@we1[9:])^T
// ---------------------------------------------------------------------------
__global__ void __launch_bounds__(128) k_aiaj(
    const float* __restrict__ bbox, const float* __restrict__ dirs,
    const float* __restrict__ prio,
    const float* __restrict__ we1, const float* __restrict__ be1) {
    const int bn = blockIdx.x;
    const int b = bn >> 6, n = bn & 63;
    __shared__ float attr[9];
    const int t = threadIdx.x;
    if (t < 4)       attr[t] = bbox[bn * 4 + t] * (1.f / 1024.f);
    else if (t < 8)  attr[t] = dirs[bn * 4 + t - 4];
    else if (t == 8) attr[8] = prio[bn];
    __syncthreads();
    if (t < 64) {
        float a = be1[t];
        #pragma unroll
        for (int d = 0; d < 9; d++) a += attr[d] * we1[d * 64 + t];
        g_Ai[bn * 64 + t] = a;
    } else {
        const int cx = t - 64;
        float a = 0.f;
        #pragma unroll
        for (int d = 0; d < 9; d++) a += attr[d] * we1[(9 + d) * 64 + cx];
        g_AjT[b * 4096 + cx * 64 + n] = a;
    }
}

// ---------------------------------------------------------------------------
// K5: edge layers 2+3.  Block = (b,i, half of j).  2048 blocks x 256 thr.
//   e1[p][k] = relu(Ai[i][k] + Aj[j0+p][k])  (smem)
//   e2 = relu(e1 @ we2 + be2)                (f32x2 MAC, we2 in smem)
//   rel = sigmoid(e2 @ wei + bei)            -> g_rel
// ---------------------------------------------------------------------------
__global__ void __launch_bounds__(256) k_edge(
    const float* __restrict__ we2, const float* __restrict__ be2,
    const float* __restrict__ wei, const float* __restrict__ bei) {
    const int blk = blockIdx.x;
    const int bi  = blk >> 1;          // b*64 + i
    const int b   = bi >> 6;
    const int j0  = (blk & 1) * 32;
    const int t   = threadIdx.x;
    __shared__ alignas(16) float ws[64 * 64];    // we2 [k][c]
    __shared__ alignas(16) float e1s[64 * 32];   // [k][p]
    __shared__ float e2s[32 * 65];               // [p][c], padded
    __shared__ float weis[64 * 8];
    __shared__ float beis[8], be2s[64], Ais[64];

    for (int i = t; i < 4096; i += 256) ws[i] = we2[i];
    for (int i = t; i < 512;  i += 256) weis[i] = wei[i];
    if (t < 8)  beis[t] = bei[t];
    if (t < 64) { be2s[t] = be2[t]; Ais[t] = g_Ai[(size_t)bi * 64 + t]; }
    __syncthreads();

    // e1 (coalesced AjT gather)
    for (int i = t; i < 2048; i += 256) {
        const int p = i & 31, k = i >> 5;
        const float aj = g_AjT[b * 4096 + k * 64 + j0 + p];
        e1s[k * 32 + p] = fmaxf(Ais[k] + aj, 0.f);
    }
    __syncthreads();

    // layer2
    const int c  = t & 63;
    const int pg = t >> 6;
    float2 acc[4] = {{0.f,0.f},{0.f,0.f},{0.f,0.f},{0.f,0.f}};
    #pragma unroll
    for (int k = 0; k < 64; k++) {
        const float w = ws[k * 64 + c];
        const float2 w2 = make_float2(w, w);
        #pragma unroll
        for (int q = 0; q < 4; q++) {
            float2 a = *(const float2*)&e1s[k * 32 + pg * 8 + q * 2];
            acc[q] = ffma2(a, w2, acc[q]);
        }
    }
    const float bb = be2s[c];
    #pragma unroll
    for (int q = 0; q < 4; q++) {
        const int p = pg * 8 + q * 2;
        e2s[(p    ) * 65 + c] = fmaxf(acc[q].x + bb, 0.f);
        e2s[(p + 1) * 65 + c] = fmaxf(acc[q].y + bb, 0.f);
    }
    __syncthreads();

    // layer3 + sigmoid: 32 pairs x 8 outputs
    const int p = t >> 3, r = t & 7;
    float a3 = beis[r];
    #pragma unroll
    for (int k = 0; k < 64; k++) a3 += e2s[p * 65 + k] * weis[k * 8 + r];
    const float rv = 1.f / (1.f + __expf(-a3));
    g_rel[((size_t)bi * 64 + j0 + p) * 8 + r] = rv;   // rel[b][i][j][r]
}

// ---------------------------------------------------------------------------
// K6: node_concepts gather: out[bi][j][u] = node_c[b][see[bi][j]][u] * mask
// ---------------------------------------------------------------------------
__global__ void __launch_bounds__(128) k_node_out(float* __restrict__ out) {
    const int bi = blockIdx.x;
    const int b  = bi >> 6;
    __shared__ int   ssee[64];
    __shared__ float sm[64];
    const int t = threadIdx.x;
    if (t < 64) {
        ssee[t] = g_see[bi * 64 + t];
        sm[t]   = (t < g_cnt[bi]) ? 1.f : 0.f;
    }
    __syncthreads();
    const int j = t >> 1, q = t & 1;
    const int s = ssee[j];
    float4 v = *(const float4*)&g_node[((size_t)b * 64 + s) * 8 + q * 4];
    const float m = sm[j];
    v.x *= m; v.y *= m; v.z *= m; v.w *= m;
    *(float4*)&out[(size_t)bi * 512 + j * 8 + q * 4] = v;
}

// ---------------------------------------------------------------------------
// K7: edge_concepts gather (DRAM-write bound, rel is L2-resident):
// out[bi][j][k][r] = rel[b][see[bi][j]][see[bi][k]][r] * m(j)*m(k)
// ---------------------------------------------------------------------------
__global__ void __launch_bounds__(256) k_edge_out(float* __restrict__ out) {
    const int bi = blockIdx.x;
    const int b  = bi >> 6;
    __shared__ int   ssee[64];
    __shared__ float sm[64];
    const int t = threadIdx.x;
    if (t < 64) {
        ssee[t] = g_see[bi * 64 + t];
        sm[t]   = (t < g_cnt[bi]) ? 1.f : 0.f;
    }
    __syncthreads();
    const float4* rel4 = (const float4*)g_rel;
    float4* out4 = (float4*)(out + NODE_OUT) + (size_t)bi * 8192;
    #pragma unroll 4
    for (int idx = t; idx < 4096; idx += 256) {
        const int j = idx >> 6, k = idx & 63;
        const int sj = ssee[j], sk = ssee[k];
        const float m = sm[j] * sm[k];
        const int ro = (b * 4096 + sj * 64 + sk) * 2;
        float4 r0 = rel4[ro], r1 = rel4[ro + 1];
        r0.x *= m; r0.y *= m; r0.z *= m; r0.w *= m;
        r1.x *= m; r1.y *= m; r1.z *= m; r1.w *= m;
        out4[idx * 2]     = r0;
        out4[idx * 2 + 1] = r1;
    }
}

// ---------------------------------------------------------------------------
extern "C" void kernel_launch(void* const* d_in, const int* in_sizes, int n_in,
                              void* d_out, int out_size) {
    const float* roi  = (const float*)d_in[0];
    const float* bbox = (const float*)d_in[1];
    const float* dirs = (const float*)d_in[2];
    const float* prio = (const float*)d_in[3];
    const float* w1   = (const float*)d_in[4];
    const float* b1   = (const float*)d_in[5];
    const float* bn1g = (const float*)d_in[6];
    const float* bn1b = (const float*)d_in[7];
    const float* bn1m = (const float*)d_in[8];
    const float* bn1v = (const float*)d_in[9];
    const float* w2   = (const float*)d_in[10];
    const float* b2   = (const float*)d_in[11];
    const float* bn2g = (const float*)d_in[12];
    const float* bn2b = (const float*)d_in[13];
    const float* bn2m = (const float*)d_in[14];
    const float* bn2v = (const float*)d_in[15];
    const float* w3   = (const float*)d_in[16];
    const float* b3   = (const float*)d_in[17];
    const float* wn   = (const float*)d_in[18];
    const float* bnc  = (const float*)d_in[19];
    const float* we1  = (const float*)d_in[20];
    const float* be1  = (const float*)d_in[21];
    const float* we2  = (const float*)d_in[22];
    const float* be2  = (const float*)d_in[23];
    const float* wei  = (const float*)d_in[24];
    const float* bei  = (const float*)d_in[25];
    const int* edge_index = (const int*)d_in[26];
    float* out = (float*)d_out;

    k_build_see<<<Bb, 512>>>(edge_index);
    k_mlp<CIMG, H1c, 0><<<dim3(32, 4), 256>>>(roi, w1, b1, bn1g, bn1b, bn1m, bn1v);
    k_mlp<H1c,  H2c, 1><<<dim3(32, 2), 256>>>(nullptr, w2, b2, bn2g, bn2b, bn2m, bn2v);
    k_mlp3<<<32, 256>>>(w3, b3, wn, bnc);
    k_aiaj<<<ROWS, 128>>>(bbox, dirs, prio, we1, be1);
    k_edge<<<2 * ROWS, 256>>>(we2, be2, wei, bei);
    k_node_out<<<ROWS, 128>>>(out);
    k_edge_out<<<ROWS, 256>>>(out);
}

// round 2
// speedup vs baseline: 1.1385x; 1.1385x over previous
#include <cuda_runtime.h>
#include <cstdint>

// ---------------------------------------------------------------------------
// GroundingNet  B=16 N=64 E=512 — 3-phase fused implementation
//  phase1: [blk 0..15]  build see/cnt   [16..31] edge layer1 decomp (Ai/AjT)
//          [32..159]    node layer1 (512->256, bn+relu)
//  phase2: [blk 0..511] edge layers 2+3 (2 i's per block, 8x8 reg tiles)
//          [512..639]   node layers 2+3+head (8 rows per block, smem-fused)
//  phase3: [1024 blks]  node_concepts + edge_concepts gather/write (DRAM-bound)
// ---------------------------------------------------------------------------

#define DINL __device__ __forceinline__

constexpr int Bb = 16, Nn = 64, Ee = 512;
constexpr int CIMG = 512, H1c = 256, H2c = 128, H3c = 64;
constexpr int ROWS = Bb * Nn;             // 1024
constexpr int NODE_OUT = ROWS * Nn * 8;   // 524288

// scratch
__device__ float g_h1[ROWS * H1c];
__device__ float g_node[ROWS * 8];
__device__ float g_Ai[ROWS * 64];
__device__ float g_AjT[Bb * 64 * 64];       // [b][k][j]
__device__ float g_rel[Bb * 64 * 64 * 8];   // 2 MB (L2-resident)
__device__ int   g_see[Bb * 64 * 64];
__device__ int   g_cnt[Bb * 64];

// packed fp32x2 FMA (sm_100+)
DINL float2 ffma2(float2 a, float2 b, float2 c) {
    float2 d;
    asm("fma.rn.f32x2 %0, %1, %2, %3;"
        : "=l"(reinterpret_cast<unsigned long long&>(d))
        : "l"(reinterpret_cast<unsigned long long&>(a)),
          "l"(reinterpret_cast<unsigned long long&>(b)),
          "l"(reinterpret_cast<unsigned long long&>(c)));
    return d;
}
DINL float sigmoidf_(float x) { return 1.f / (1.f + __expf(-x)); }

// ===========================================================================
// PHASE 1
// ===========================================================================
__global__ void __launch_bounds__(256) k_phase1(
    const int*   __restrict__ edge_index,
    const float* __restrict__ roi,
    const float* __restrict__ w1,  const float* __restrict__ b1,
    const float* __restrict__ bng, const float* __restrict__ bnb,
    const float* __restrict__ bnm, const float* __restrict__ bnv,
    const float* __restrict__ bbox, const float* __restrict__ dirs,
    const float* __restrict__ prio,
    const float* __restrict__ we1, const float* __restrict__ be1) {
    __shared__ union {
        struct { float xs[64 * 32]; float ws[64 * 64]; } m;   // 24 KB
        struct { int ssrc[512]; int sdst[512]; } s;
        struct { float attr[64 * 9]; } a;
    } sm;
    const int blk = blockIdx.x, t = threadIdx.x;

    if (blk < 16) {
        // ---------------- build see / cnt ----------------
        const int b = blk;
        const int* ei = edge_index + (size_t)b * 2 * Ee;
        for (int e = t; e < Ee; e += 256) { sm.s.ssrc[e] = ei[e]; sm.s.sdst[e] = ei[Ee + e]; }
        for (int i = t; i < Nn * Nn; i += 256)
            g_see[b * 4096 + i] = ((i & 63) == 0) ? (i >> 6) : 0;
        __syncthreads();
        if (t < 64) {
            int d = 0;
            #pragma unroll 8
            for (int e = 0; e < Ee; e++) d += (sm.s.sdst[e] == t);
            g_cnt[b * 64 + t] = min(d + 1, 64);
        }
        for (int e = t; e < Ee; e += 256) {
            const int dst = sm.s.sdst[e];
            int p = 1;
            for (int e2 = 0; e2 < e; e2++) p += (sm.s.sdst[e2] == dst);
            if (p < 64) g_see[b * 4096 + dst * 64 + p] = sm.s.ssrc[e];
        }
    } else if (blk < 32) {
        // ---------------- edge layer1 decomposition ----------------
        const int b = blk - 16;
        for (int i = t; i < 576; i += 256) {
            const int n = i / 9, d = i - n * 9;
            float v = (d < 4) ? bbox[(b * 64 + n) * 4 + d] * (1.f / 1024.f)
                    : (d < 8) ? dirs[(b * 64 + n) * 4 + d - 4]
                              : prio[b * 64 + n];
            sm.a.attr[i] = v;
        }
        __syncthreads();
        const int c = t & 63, q = t >> 6;
        float wA[9], wB[9];
        #pragma unroll
        for (int d = 0; d < 9; d++) { wA[d] = we1[d * 64 + c]; wB[d] = we1[(9 + d) * 64 + c]; }
        const float bc = be1[c];
        for (int n = q; n < 64; n += 4) {
            float ai = bc, aj = 0.f;
            #pragma unroll
            for (int d = 0; d < 9; d++) {
                const float a = sm.a.attr[n * 9 + d];
                ai += a * wA[d]; aj += a * wB[d];
            }
            g_Ai[(b * 64 + n) * 64 + c] = ai;
            g_AjT[b * 4096 + c * 64 + n] = aj;
        }
    } else {
        // ---------------- node layer1: 32 rows x 64 cols ----------------
        const int id = blk - 32;
        const int r0 = (id & 31) * 32, c0 = (id >> 5) * 64;
        const int cc = t & 63, c = c0 + cc, pg = t >> 6;
        float2 acc[4] = {{0.f,0.f},{0.f,0.f},{0.f,0.f},{0.f,0.f}};
        for (int kc = 0; kc < CIMG; kc += 64) {
            for (int i = t; i < 512; i += 256) {
                const int r = i >> 4, k4 = (i & 15) << 2;
                float4 xv = *(const float4*)&roi[(size_t)(r0 + r) * CIMG + kc + k4];
                sm.m.xs[(k4 + 0) * 32 + r] = xv.x;
                sm.m.xs[(k4 + 1) * 32 + r] = xv.y;
                sm.m.xs[(k4 + 2) * 32 + r] = xv.z;
                sm.m.xs[(k4 + 3) * 32 + r] = xv.w;
            }
            for (int i = t; i < 1024; i += 256) {
                const int k = i >> 4, c4 = (i & 15) << 2;
                *(float4*)&sm.m.ws[k * 64 + c4] =
                    *(const float4*)&w1[(size_t)(kc + k) * H1c + c0 + c4];
            }
            __syncthreads();
            #pragma unroll
            for (int k = 0; k < 64; k++) {
                const float w = sm.m.ws[k * 64 + cc];
                const float2 w2 = make_float2(w, w);
                #pragma unroll
                for (int q = 0; q < 4; q++) {
                    float2 a = *(const float2*)&sm.m.xs[k * 32 + pg * 8 + q * 2];
                    acc[q] = ffma2(a, w2, acc[q]);
                }
            }
            __syncthreads();
        }
        const float s  = bng[c] * rsqrtf(bnv[c] + 1e-5f);
        const float sh = bnb[c] - bnm[c] * s;
        const float bc = b1[c];
        #pragma unroll
        for (int q = 0; q < 4; q++) {
            const int row = pg * 8 + q * 2;
            g_h1[(size_t)(r0 + row    ) * H1c + c] = fmaxf((acc[q].x + bc) * s + sh, 0.f);
            g_h1[(size_t)(r0 + row + 1) * H1c + c] = fmaxf((acc[q].y + bc) * s + sh, 0.f);
        }
    }
}

// ===========================================================================
// PHASE 2 : dynamic smem (85280 B)
// ===========================================================================
constexpr int P2_SMEM = 21320 * 4;   // floats: ws4096|e1s8192|e2s8320|wei512|be2 64|bei 8|Ai 128

__global__ void __launch_bounds__(128) k_phase2(
    const float* __restrict__ we2, const float* __restrict__ be2,
    const float* __restrict__ wei, const float* __restrict__ bei,
    const float* __restrict__ w2,  const float* __restrict__ b2,
    const float* __restrict__ bn2g, const float* __restrict__ bn2b,
    const float* __restrict__ bn2m, const float* __restrict__ bn2v,
    const float* __restrict__ w3,  const float* __restrict__ b3,
    const float* __restrict__ wn,  const float* __restrict__ bnc) {
    extern __shared__ float dyn[];
    const int blk = blockIdx.x, t = threadIdx.x;

    if (blk < 512) {
        // ---------------- edge layers 2+3, two i's per block ----------------
        float* ws   = dyn;             // we2 [k][c] 4096
        float* e1s  = dyn + 4096;      // [ig][k][j] 8192
        float* e2s  = dyn + 12288;     // [ig][j][c] stride 65, 8320
        float* weis = dyn + 20608;     // 512
        float* be2s = dyn + 21120;     // 64
        float* beis = dyn + 21184;     // 8
        float* Ais  = dyn + 21192;     // 128
        const int bi0 = blk * 2, b = bi0 >> 6;

        for (int i = t; i < 4096; i += 128) ws[i] = we2[i];
        for (int i = t; i < 512;  i += 128) weis[i] = wei[i];
        if (t < 64) be2s[t] = be2[t];
        if (t < 8)  beis[t] = bei[t];
        Ais[t] = g_Ai[(size_t)bi0 * 64 + t];
        __syncthreads();

        for (int i = t; i < 8192; i += 128) {
            const int ig = i >> 12, idx = i & 4095, k = idx >> 6, j = idx & 63;
            e1s[i] = fmaxf(Ais[ig * 64 + k] + g_AjT[b * 4096 + k * 64 + j], 0.f);
        }
        __syncthreads();

        // layer2: 8x8 register tile. 64 threads per i.
        const int ig = t >> 6, tt = t & 63;
        const int cg = tt & 7, jg = tt >> 3;
        const int c0 = cg * 8, j0 = jg * 8;
        const float* e1b = e1s + ig * 4096;
        float2 acc[8][4];
        #pragma unroll
        for (int ci = 0; ci < 8; ci++)
            #pragma unroll
            for (int jp = 0; jp < 4; jp++) acc[ci][jp] = make_float2(0.f, 0.f);

        #pragma unroll 4
        for (int k = 0; k < 64; k++) {
            const float4 a0 = *(const float4*)&e1b[k * 64 + j0];
            const float4 a1 = *(const float4*)&e1b[k * 64 + j0 + 4];
            float2 aj[4] = {{a0.x,a0.y},{a0.z,a0.w},{a1.x,a1.y},{a1.z,a1.w}};
            const float4 w0 = *(const float4*)&ws[k * 64 + c0];
            const float4 w1v = *(const float4*)&ws[k * 64 + c0 + 4];
            const float wv[8] = {w0.x,w0.y,w0.z,w0.w,w1v.x,w1v.y,w1v.z,w1v.w};
            #pragma unroll
            for (int ci = 0; ci < 8; ci++) {
                const float2 w2f = make_float2(wv[ci], wv[ci]);
                #pragma unroll
                for (int jp = 0; jp < 4; jp++)
                    acc[ci][jp] = ffma2(aj[jp], w2f, acc[ci][jp]);
            }
        }
        // relu + bias -> e2s (stride 65, conflict-free layer3 reads)
        float* e2b = e2s + ig * 4160;
        #pragma unroll
        for (int ci = 0; ci < 8; ci++) {
            const float bb = be2s[c0 + ci];
            #pragma unroll
            for (int jp = 0; jp < 4; jp++) {
                e2b[(j0 + jp * 2    ) * 65 + c0 + ci] = fmaxf(acc[ci][jp].x + bb, 0.f);
                e2b[(j0 + jp * 2 + 1) * 65 + c0 + ci] = fmaxf(acc[ci][jp].y + bb, 0.f);
            }
        }
        __syncthreads();

        // layer3 + sigmoid: thread = (ig, j)
        const float* e2r = e2s + ig * 4160 + tt * 65;
        float a3[8];
        #pragma unroll
        for (int r = 0; r < 8; r++) a3[r] = beis[r];
        #pragma unroll 4
        for (int k = 0; k < 64; k++) {
            const float v = e2r[k];
            #pragma unroll
            for (int r = 0; r < 8; r++) a3[r] += v * weis[k * 8 + r];
        }
        float* dst = &g_rel[(((size_t)bi0 + ig) * 64 + tt) * 8];
        float4 o0 = make_float4(sigmoidf_(a3[0]), sigmoidf_(a3[1]), sigmoidf_(a3[2]), sigmoidf_(a3[3]));
        float4 o1 = make_float4(sigmoidf_(a3[4]), sigmoidf_(a3[5]), sigmoidf_(a3[6]), sigmoidf_(a3[7]));
        *(float4*)dst = o0;
        *(float4*)(dst + 4) = o1;
    } else {
        // ---------------- node layers 2+3+head, 8 rows per block ----------------
        const int id = blk - 512;         // 0..127
        const int r0 = id * 8;
        float* xs   = dyn;                // [k][r] 256*8
        float* h2sT = dyn + 2048;         // [c2][r] 128*8
        float* h3sT = dyn + 3072;         // [c3][r] 64*8

        for (int i = t; i < 512; i += 128) {
            const int r = i >> 6, k4 = (i & 63) << 2;
            float4 xv = *(const float4*)&g_h1[(size_t)(r0 + r) * H1c + k4];
            xs[(k4 + 0) * 8 + r] = xv.x;
            xs[(k4 + 1) * 8 + r] = xv.y;
            xs[(k4 + 2) * 8 + r] = xv.z;
            xs[(k4 + 3) * 8 + r] = xv.w;
        }
        __syncthreads();
        {   // layer2: c = t (128 cols), 8 rows in regs
            const int c = t;
            float2 acc[4] = {{0.f,0.f},{0.f,0.f},{0.f,0.f},{0.f,0.f}};
            #pragma unroll 4
            for (int k = 0; k < H1c; k++) {
                const float w = __ldg(&w2[k * H2c + c]);
                const float2 wv = make_float2(w, w);
                const float4 x0 = *(const float4*)&xs[k * 8];
                const float4 x1 = *(const float4*)&xs[k * 8 + 4];
                acc[0] = ffma2(make_float2(x0.x, x0.y), wv, acc[0]);
                acc[1] = ffma2(make_float2(x0.z, x0.w), wv, acc[1]);
                acc[2] = ffma2(make_float2(x1.x, x1.y), wv, acc[2]);
                acc[3] = ffma2(make_float2(x1.z, x1.w), wv, acc[3]);
            }
            const float s  = bn2g[c] * rsqrtf(bn2v[c] + 1e-5f);
            const float sh = bn2b[c] - bn2m[c] * s;
            const float bb = b2[c];
            #pragma unroll
            for (int q = 0; q < 4; q++) {
                h2sT[c * 8 + q * 2]     = fmaxf((acc[q].x + bb) * s + sh, 0.f);
                h2sT[c * 8 + q * 2 + 1] = fmaxf((acc[q].y + bb) * s + sh, 0.f);
            }
        }
        __syncthreads();
        {   // layer3: c3 = t&63, rg = t>>6 -> rows rg*4..rg*4+3
            const int c3 = t & 63, rg = t >> 6;
            float2 acc[2] = {{0.f,0.f},{0.f,0.f}};
            #pragma unroll 4
            for (int k = 0; k < H2c; k++) {
                const float w = __ldg(&w3[k * H3c + c3]);
                const float2 wv = make_float2(w, w);
                const float4 x = *(const float4*)&h2sT[k * 8 + rg * 4];
                acc[0] = ffma2(make_float2(x.x, x.y), wv, acc[0]);
                acc[1] = ffma2(make_float2(x.z, x.w), wv, acc[1]);
            }
            const float bb = b3[c3];
            h3sT[c3 * 8 + rg * 4 + 0] = fmaxf(acc[0].x + bb, 0.f);
            h3sT[c3 * 8 + rg * 4 + 1] = fmaxf(acc[0].y + bb, 0.f);
            h3sT[c3 * 8 + rg * 4 + 2] = fmaxf(acc[1].x + bb, 0.f);
            h3sT[c3 * 8 + rg * 4 + 3] = fmaxf(acc[1].y + bb, 0.f);
        }
        __syncthreads();
        if (t < 64) {   // head: 8 rows x 8 u
            const int row = t >> 3, u = t & 7;
            float a = __ldg(&bnc[u]);
            #pragma unroll 8
            for (int k = 0; k < 64; k++) a += h3sT[k * 8 + row] * __ldg(&wn[k * 8 + u]);
            g_node[(size_t)(r0 + row) * 8 + u] = sigmoidf_(a);
        }
    }
}

// ===========================================================================
// PHASE 3 : outputs (DRAM-write bound)
// ===========================================================================
__global__ void __launch_bounds__(256) k_phase3(float* __restrict__ out) {
    const int bi = blockIdx.x, b = bi >> 6, t = threadIdx.x;
    __shared__ int   ssee[64];
    __shared__ float smk[64];
    if (t < 64) {
        ssee[t] = g_see[bi * 64 + t];
        smk[t]  = (t < g_cnt[bi]) ? 1.f : 0.f;
    }
    __syncthreads();
    if (t < 128) {  // node_concepts row
        const int j = t >> 1, q = t & 1;
        float4 v = *(const float4*)&g_node[((size_t)b * 64 + ssee[j]) * 8 + q * 4];
        const float m = smk[j];
        v.x *= m; v.y *= m; v.z *= m; v.w *= m;
        *(float4*)&out[(size_t)bi * 512 + j * 8 + q * 4] = v;
    }
    const float4* rel4 = (const float4*)g_rel;
    float4* out4 = (float4*)(out + NODE_OUT) + (size_t)bi * 8192;
    #pragma unroll 4
    for (int idx = t; idx < 4096; idx += 256) {
        const int j = idx >> 6, k = idx & 63;
        const float m = smk[j] * smk[k];
        const int ro = (b * 4096 + ssee[j] * 64 + ssee[k]) * 2;
        float4 r0 = rel4[ro], r1 = rel4[ro + 1];
        r0.x *= m; r0.y *= m; r0.z *= m; r0.w *= m;
        r1.x *= m; r1.y *= m; r1.z *= m; r1.w *= m;
        out4[idx * 2]     = r0;
        out4[idx * 2 + 1] = r1;
    }
}

// ===========================================================================
extern "C" void kernel_launch(void* const* d_in, const int* in_sizes, int n_in,
                              void* d_out, int out_size) {
    const float* roi  = (const float*)d_in[0];
    const float* bbox = (const float*)d_in[1];
    const float* dirs = (const float*)d_in[2];
    const float* prio = (const float*)d_in[3];
    const float* w1   = (const float*)d_in[4];
    const float* b1   = (const float*)d_in[5];
    const float* bn1g = (const float*)d_in[6];
    const float* bn1b = (const float*)d_in[7];
    const float* bn1m = (const float*)d_in[8];
    const float* bn1v = (const float*)d_in[9];
    const float* w2   = (const float*)d_in[10];
    const float* b2   = (const float*)d_in[11];
    const float* bn2g = (const float*)d_in[12];
    const float* bn2b = (const float*)d_in[13];
    const float* bn2m = (const float*)d_in[14];
    const float* bn2v = (const float*)d_in[15];
    const float* w3   = (const float*)d_in[16];
    const float* b3   = (const float*)d_in[17];
    const float* wn   = (const float*)d_in[18];
    const float* bnc  = (const float*)d_in[19];
    const float* we1  = (const float*)d_in[20];
    const float* be1  = (const float*)d_in[21];
    const float* we2  = (const float*)d_in[22];
    const float* be2  = (const float*)d_in[23];
    const float* wei  = (const float*)d_in[24];
    const float* bei  = (const float*)d_in[25];
    const int* edge_index = (const int*)d_in[26];
    float* out = (float*)d_out;

    cudaFuncSetAttribute(k_phase2, cudaFuncAttributeMaxDynamicSharedMemorySize, P2_SMEM);

    k_phase1<<<160, 256>>>(edge_index, roi, w1, b1, bn1g, bn1b, bn1m, bn1v,
                           bbox, dirs, prio, we1, be1);
    k_phase2<<<640, 128, P2_SMEM>>>(we2, be2, wei, bei,
                                    w2, b2, bn2g, bn2b, bn2m, bn2v,
                                    w3, b3, wn, bnc);
    k_phase3<<<1024, 256>>>(out);
}

// round 3
// speedup vs baseline: 1.4931x; 1.3114x over previous
#include <cuda_runtime.h>
#include <cstdint>

// ---------------------------------------------------------------------------
// GroundingNet  B=16 N=64 E=512 — 3-phase, issue-bound-optimized
//  phase1: [0..127] node layer1 (32x64 tiles, 4x2 thread tiles)
//          [128..143] see/cnt (O(E*N) smem scan)  [144..159] edge layer1 decomp
//  phase2: [0..1023] edge layers 2+3 (1 bi/block, 4x4 reg tiles, 36KB smem)
//          [1024..1151] node layers 2+3+head
//  phase3: [1024] gather + write outputs (DRAM-bound)
// ---------------------------------------------------------------------------

#define DINL __device__ __forceinline__

constexpr int Bb = 16, Nn = 64, Ee = 512;
constexpr int CIMG = 512, H1c = 256, H2c = 128, H3c = 64;
constexpr int ROWS = Bb * Nn;             // 1024
constexpr int NODE_OUT = ROWS * Nn * 8;   // 524288

__device__ float g_h1[ROWS * H1c];
__device__ float g_node[ROWS * 8];
__device__ float g_Ai[ROWS * 64];
__device__ float g_AjT[Bb * 64 * 64];       // [b][k][j]
__device__ float g_rel[Bb * 64 * 64 * 8];   // 2 MB (L2-resident)
__device__ int   g_see[Bb * 64 * 64];
__device__ int   g_cnt[Bb * 64];

DINL float2 ffma2(float2 a, float2 b, float2 c) {
    float2 d;
    asm("fma.rn.f32x2 %0, %1, %2, %3;"
        : "=l"(reinterpret_cast<unsigned long long&>(d))
        : "l"(reinterpret_cast<unsigned long long&>(a)),
          "l"(reinterpret_cast<unsigned long long&>(b)),
          "l"(reinterpret_cast<unsigned long long&>(c)));
    return d;
}
DINL float sigmoidf_(float x) { return 1.f / (1.f + __expf(-x)); }

// ===========================================================================
// PHASE 1
// ===========================================================================
__global__ void __launch_bounds__(256) k_phase1(
    const int*   __restrict__ edge_index,
    const float* __restrict__ roi,
    const float* __restrict__ w1,  const float* __restrict__ b1,
    const float* __restrict__ bng, const float* __restrict__ bnb,
    const float* __restrict__ bnm, const float* __restrict__ bnv,
    const float* __restrict__ bbox, const float* __restrict__ dirs,
    const float* __restrict__ prio,
    const float* __restrict__ we1, const float* __restrict__ be1) {
    __shared__ union {
        struct { float xs[64 * 36]; float ws[64 * 64]; } m;          // 25.6 KB
        struct { int ssrc[512]; int sdst[512]; int srow[4096]; } s;  // 20.5 KB
        struct { float attr[64 * 9]; } a;
    } sm;
    const int blk = blockIdx.x, t = threadIdx.x;

    if (blk < 128) {
        // ------------- node layer1: 32 rows x 64 cols, thread 4x2 -------------
        const int r0 = (blk & 31) * 32, c0 = (blk >> 5) * 64;
        const int tr = t >> 5;        // 0..7  -> rows tr*4..+3
        const int tc = t & 31;        // cols tc*2, tc*2+1
        float2 a01[2] = {{0.f,0.f},{0.f,0.f}};   // rows 0,1 x cols 0,1
        float2 a23[2] = {{0.f,0.f},{0.f,0.f}};   // rows 2,3
        for (int kc = 0; kc < CIMG; kc += 64) {
            for (int i = t; i < 512; i += 256) {
                const int r = i >> 4, k4 = (i & 15) << 2;
                float4 v = *(const float4*)&roi[(size_t)(r0 + r) * CIMG + kc + k4];
                sm.m.xs[(k4 + 0) * 36 + r] = v.x;
                sm.m.xs[(k4 + 1) * 36 + r] = v.y;
                sm.m.xs[(k4 + 2) * 36 + r] = v.z;
                sm.m.xs[(k4 + 3) * 36 + r] = v.w;
            }
            for (int i = t; i < 1024; i += 256) {
                const int k = i >> 4, c4 = (i & 15) << 2;
                *(float4*)&sm.m.ws[k * 64 + c4] =
                    *(const float4*)&w1[(size_t)(kc + k) * H1c + c0 + c4];
            }
            __syncthreads();
            #pragma unroll 16
            for (int k = 0; k < 64; k++) {
                const float4 a = *(const float4*)&sm.m.xs[k * 36 + tr * 4];
                const float2 w = *(const float2*)&sm.m.ws[k * 64 + tc * 2];
                const float2 wx = make_float2(w.x, w.x), wy = make_float2(w.y, w.y);
                a01[0] = ffma2(make_float2(a.x, a.y), wx, a01[0]);
                a01[1] = ffma2(make_float2(a.x, a.y), wy, a01[1]);
                a23[0] = ffma2(make_float2(a.z, a.w), wx, a23[0]);
                a23[1] = ffma2(make_float2(a.z, a.w), wy, a23[1]);
            }
            __syncthreads();
        }
        const int c = c0 + tc * 2;
        float s0 = bng[c]     * rsqrtf(bnv[c]     + 1e-5f);
        float s1 = bng[c + 1] * rsqrtf(bnv[c + 1] + 1e-5f);
        float h0 = bnb[c]     - bnm[c]     * s0;
        float h1 = bnb[c + 1] - bnm[c + 1] * s1;
        float q0 = b1[c], q1 = b1[c + 1];
        const int row = r0 + tr * 4;
        float2 o;
        o = make_float2(fmaxf((a01[0].x + q0) * s0 + h0, 0.f), fmaxf((a01[1].x + q1) * s1 + h1, 0.f));
        *(float2*)&g_h1[(size_t)(row + 0) * H1c + c] = o;
        o = make_float2(fmaxf((a01[0].y + q0) * s0 + h0, 0.f), fmaxf((a01[1].y + q1) * s1 + h1, 0.f));
        *(float2*)&g_h1[(size_t)(row + 1) * H1c + c] = o;
        o = make_float2(fmaxf((a23[0].x + q0) * s0 + h0, 0.f), fmaxf((a23[1].x + q1) * s1 + h1, 0.f));
        *(float2*)&g_h1[(size_t)(row + 2) * H1c + c] = o;
        o = make_float2(fmaxf((a23[0].y + q0) * s0 + h0, 0.f), fmaxf((a23[1].y + q1) * s1 + h1, 0.f));
        *(float2*)&g_h1[(size_t)(row + 3) * H1c + c] = o;
    } else if (blk < 144) {
        // ------------------- build see / cnt: per-dst scan -------------------
        const int b = blk - 128;
        const int* ei = edge_index + (size_t)b * 2 * Ee;
        for (int e = t; e < Ee; e += 256) { sm.s.ssrc[e] = ei[e]; sm.s.sdst[e] = ei[Ee + e]; }
        for (int i = t; i < 4096; i += 256)
            sm.s.srow[i] = ((i & 63) == 0) ? (i >> 6) : 0;
        __syncthreads();
        if (t < 64) {
            const int n = t;
            int p = 1;
            #pragma unroll 8
            for (int e = 0; e < Ee; e++) {
                if (sm.s.sdst[e] == n) {
                    if (p < 64) sm.s.srow[n * 64 + p] = sm.s.ssrc[e];
                    p++;
                }
            }
            g_cnt[b * 64 + n] = min(p, 64);
        }
        __syncthreads();
        for (int i = t; i < 1024; i += 256)
            *(int4*)&g_see[b * 4096 + i * 4] = *(const int4*)&sm.s.srow[i * 4];
    } else {
        // ------------------- edge layer1 decomposition -------------------
        const int b = blk - 144;
        for (int i = t; i < 576; i += 256) {
            const int n = i / 9, d = i - n * 9;
            float v = (d < 4) ? bbox[(b * 64 + n) * 4 + d] * (1.f / 1024.f)
                    : (d < 8) ? dirs[(b * 64 + n) * 4 + d - 4]
                              : prio[b * 64 + n];
            sm.a.attr[i] = v;
        }
        __syncthreads();
        const int c = t & 63, q = t >> 6;
        float wA[9], wB[9];
        #pragma unroll
        for (int d = 0; d < 9; d++) { wA[d] = we1[d * 64 + c]; wB[d] = we1[(9 + d) * 64 + c]; }
        const float bc = be1[c];
        for (int n = q; n < 64; n += 4) {
            float ai = bc, aj = 0.f;
            #pragma unroll
            for (int d = 0; d < 9; d++) {
                const float a = sm.a.attr[n * 9 + d];
                ai += a * wA[d]; aj += a * wB[d];
            }
            g_Ai[(b * 64 + n) * 64 + c] = ai;
            g_AjT[b * 4096 + c * 64 + n] = aj;
        }
    }
}

// ===========================================================================
// PHASE 2
// ===========================================================================
__global__ void __launch_bounds__(256) k_phase2(
    const float* __restrict__ we2, const float* __restrict__ be2,
    const float* __restrict__ wei, const float* __restrict__ bei,
    const float* __restrict__ w2,  const float* __restrict__ b2,
    const float* __restrict__ bn2g, const float* __restrict__ bn2b,
    const float* __restrict__ bn2m, const float* __restrict__ bn2v,
    const float* __restrict__ w3,  const float* __restrict__ b3,
    const float* __restrict__ wn,  const float* __restrict__ bnc) {
    __shared__ union {
        struct {
            float ws[64 * 64];      // we2 [k][c]
            float e1[64 * 68];      // [k][j] (later aliased as e2 [j][c])
            float weis[512];
            float be2s[64], Ais[64], beis[8];
        } e;                        // 36.4 KB
        struct { float xs[256 * 8]; float h2[128 * 8]; float h3[64 * 8]; } n;
    } u;
    const int blk = blockIdx.x, t = threadIdx.x;

    if (blk < 1024) {
        // ----------------- edge layers 2+3, one bi per block -----------------
        const int bi = blk, b = bi >> 6;
        float* ws  = u.e.ws;
        float* e1s = u.e.e1;
        float* e2s = u.e.e1;      // alias (e1 dead after GEMM1)
        for (int i = t; i < 1024; i += 256)
            *(float4*)&ws[i * 4] = *(const float4*)&we2[i * 4];
        for (int i = t; i < 128; i += 256) { }  // (no-op keep)
        for (int i = t; i < 512; i += 256) u.e.weis[i] = wei[i];
        if (t < 64) { u.e.be2s[t] = be2[t]; u.e.Ais[t] = g_Ai[(size_t)bi * 64 + t]; }
        if (t < 8)  u.e.beis[t] = bei[t];
        __syncthreads();
        // e1[k][j] = relu(Ai[k] + AjT[k][j])
        for (int i = t; i < 4096; i += 256) {
            const int k = i >> 6, j = i & 63;
            e1s[k * 68 + j] = fmaxf(u.e.Ais[k] + g_AjT[b * 4096 + i], 0.f);
        }
        __syncthreads();
        // GEMM1: thread tile 4j x 4c
        const int tc = t & 15, tj = t >> 4;
        float2 a01[4] = {{0.f,0.f},{0.f,0.f},{0.f,0.f},{0.f,0.f}};
        float2 a23[4] = {{0.f,0.f},{0.f,0.f},{0.f,0.f},{0.f,0.f}};
        #pragma unroll 8
        for (int k = 0; k < 64; k++) {
            const float4 a = *(const float4*)&e1s[k * 68 + tj * 4];
            const float4 w = *(const float4*)&ws[k * 64 + tc * 4];
            const float wv[4] = {w.x, w.y, w.z, w.w};
            const float2 r01 = make_float2(a.x, a.y);
            const float2 r23 = make_float2(a.z, a.w);
            #pragma unroll
            for (int ci = 0; ci < 4; ci++) {
                const float2 wc = make_float2(wv[ci], wv[ci]);
                a01[ci] = ffma2(r01, wc, a01[ci]);
                a23[ci] = ffma2(r23, wc, a23[ci]);
            }
        }
        __syncthreads();   // everyone done reading e1s
        #pragma unroll
        for (int ci = 0; ci < 4; ci++) {
            const int cc = tc * 4 + ci;
            const float bb = u.e.be2s[cc];
            e2s[(tj * 4 + 0) * 68 + cc] = fmaxf(a01[ci].x + bb, 0.f);
            e2s[(tj * 4 + 1) * 68 + cc] = fmaxf(a01[ci].y + bb, 0.f);
            e2s[(tj * 4 + 2) * 68 + cc] = fmaxf(a23[ci].x + bb, 0.f);
            e2s[(tj * 4 + 3) * 68 + cc] = fmaxf(a23[ci].y + bb, 0.f);
        }
        __syncthreads();
        // layer3 + sigmoid: thread = (j, r-pair)
        const int jj = t >> 2, rp = t & 3;
        float2 a3 = make_float2(u.e.beis[rp * 2], u.e.beis[rp * 2 + 1]);
        #pragma unroll 8
        for (int k = 0; k < 64; k++) {
            const float v = e2s[jj * 68 + k];
            const float2 wv = *(const float2*)&u.e.weis[k * 8 + rp * 2];
            a3 = ffma2(make_float2(v, v), wv, a3);
        }
        float2 o = make_float2(sigmoidf_(a3.x), sigmoidf_(a3.y));
        *(float2*)&g_rel[(((size_t)bi) * 64 + jj) * 8 + rp * 2] = o;
    } else {
        // -------------- node layers 2+3+head, 8 rows per block --------------
        const int id = blk - 1024;        // 0..127
        const int r0 = id * 8;
        float* xs = u.n.xs; float* h2sT = u.n.h2; float* h3sT = u.n.h3;
        for (int i = t; i < 512; i += 256) {
            const int r = i >> 6, k4 = (i & 63) << 2;
            float4 xv = *(const float4*)&g_h1[(size_t)(r0 + r) * H1c + k4];
            xs[(k4 + 0) * 8 + r] = xv.x;
            xs[(k4 + 1) * 8 + r] = xv.y;
            xs[(k4 + 2) * 8 + r] = xv.z;
            xs[(k4 + 3) * 8 + r] = xv.w;
        }
        __syncthreads();
        if (t < 128) {   // layer2: c = t
            const int c = t;
            float2 acc[4] = {{0.f,0.f},{0.f,0.f},{0.f,0.f},{0.f,0.f}};
            #pragma unroll 4
            for (int k = 0; k < H1c; k++) {
                const float w = __ldg(&w2[k * H2c + c]);
                const float2 wv = make_float2(w, w);
                const float4 x0 = *(const float4*)&xs[k * 8];
                const float4 x1 = *(const float4*)&xs[k * 8 + 4];
                acc[0] = ffma2(make_float2(x0.x, x0.y), wv, acc[0]);
                acc[1] = ffma2(make_float2(x0.z, x0.w), wv, acc[1]);
                acc[2] = ffma2(make_float2(x1.x, x1.y), wv, acc[2]);
                acc[3] = ffma2(make_float2(x1.z, x1.w), wv, acc[3]);
            }
            const float s  = bn2g[c] * rsqrtf(bn2v[c] + 1e-5f);
            const float sh = bn2b[c] - bn2m[c] * s;
            const float bb = b2[c];
            #pragma unroll
            for (int q = 0; q < 4; q++) {
                h2sT[c * 8 + q * 2]     = fmaxf((acc[q].x + bb) * s + sh, 0.f);
                h2sT[c * 8 + q * 2 + 1] = fmaxf((acc[q].y + bb) * s + sh, 0.f);
            }
        }
        __syncthreads();
        if (t < 128) {   // layer3
            const int c3 = t & 63, rg = t >> 6;
            float2 acc[2] = {{0.f,0.f},{0.f,0.f}};
            #pragma unroll 4
            for (int k = 0; k < H2c; k++) {
                const float w = __ldg(&w3[k * H3c + c3]);
                const float2 wv = make_float2(w, w);
                const float4 x = *(const float4*)&h2sT[k * 8 + rg * 4];
                acc[0] = ffma2(make_float2(x.x, x.y), wv, acc[0]);
                acc[1] = ffma2(make_float2(x.z, x.w), wv, acc[1]);
            }
            const float bb = b3[c3];
            h3sT[c3 * 8 + rg * 4 + 0] = fmaxf(acc[0].x + bb, 0.f);
            h3sT[c3 * 8 + rg * 4 + 1] = fmaxf(acc[0].y + bb, 0.f);
            h3sT[c3 * 8 + rg * 4 + 2] = fmaxf(acc[1].x + bb, 0.f);
            h3sT[c3 * 8 + rg * 4 + 3] = fmaxf(acc[1].y + bb, 0.f);
        }
        __syncthreads();
        if (t < 64) {   // head
            const int row = t >> 3, uu = t & 7;
            float a = __ldg(&bnc[uu]);
            #pragma unroll 8
            for (int k = 0; k < 64; k++) a += h3sT[k * 8 + row] * __ldg(&wn[k * 8 + uu]);
            g_node[(size_t)(r0 + row) * 8 + uu] = sigmoidf_(a);
        }
    }
}

// ===========================================================================
// PHASE 3 : outputs (DRAM-write bound)
// ===========================================================================
__global__ void __launch_bounds__(256) k_phase3(float* __restrict__ out) {
    const int bi = blockIdx.x, b = bi >> 6, t = threadIdx.x;
    __shared__ int   ssee[64];
    __shared__ float smk[64];
    if (t < 64) {
        ssee[t] = g_see[bi * 64 + t];
        smk[t]  = (t < g_cnt[bi]) ? 1.f : 0.f;
    }
    __syncthreads();
    if (t < 128) {  // node_concepts row
        const int j = t >> 1, q = t & 1;
        float4 v = *(const float4*)&g_node[((size_t)b * 64 + ssee[j]) * 8 + q * 4];
        const float m = smk[j];
        v.x *= m; v.y *= m; v.z *= m; v.w *= m;
        *(float4*)&out[(size_t)bi * 512 + j * 8 + q * 4] = v;
    }
    const float4* rel4 = (const float4*)g_rel;
    float4* out4 = (float4*)(out + NODE_OUT) + (size_t)bi * 8192;
    #pragma unroll 4
    for (int idx = t; idx < 4096; idx += 256) {
        const int j = idx >> 6, k = idx & 63;
        const float m = smk[j] * smk[k];
        const int ro = (b * 4096 + ssee[j] * 64 + ssee[k]) * 2;
        float4 r0 = rel4[ro], r1 = rel4[ro + 1];
        r0.x *= m; r0.y *= m; r0.z *= m; r0.w *= m;
        r1.x *= m; r1.y *= m; r1.z *= m; r1.w *= m;
        __stcs(&out4[idx * 2],     r0);
        __stcs(&out4[idx * 2 + 1], r1);
    }
}

// ===========================================================================
extern "C" void kernel_launch(void* const* d_in, const int* in_sizes, int n_in,
                              void* d_out, int out_size) {
    const float* roi  = (const float*)d_in[0];
    const float* bbox = (const float*)d_in[1];
    const float* dirs = (const float*)d_in[2];
    const float* prio = (const float*)d_in[3];
    const float* w1   = (const float*)d_in[4];
    const float* b1   = (const float*)d_in[5];
    const float* bn1g = (const float*)d_in[6];
    const float* bn1b = (const float*)d_in[7];
    const float* bn1m = (const float*)d_in[8];
    const float* bn1v = (const float*)d_in[9];
    const float* w2   = (const float*)d_in[10];
    const float* b2   = (const float*)d_in[11];
    const float* bn2g = (const float*)d_in[12];
    const float* bn2b = (const float*)d_in[13];
    const float* bn2m = (const float*)d_in[14];
    const float* bn2v = (const float*)d_in[15];
    const float* w3   = (const float*)d_in[16];
    const float* b3   = (const float*)d_in[17];
    const float* wn   = (const float*)d_in[18];
    const float* bnc  = (const float*)d_in[19];
    const float* we1  = (const float*)d_in[20];
    const float* be1  = (const float*)d_in[21];
    const float* we2  = (const float*)d_in[22];
    const float* be2  = (const float*)d_in[23];
    const float* wei  = (const float*)d_in[24];
    const float* bei  = (const float*)d_in[25];
    const int* edge_index = (const int*)d_in[26];
    float* out = (float*)d_out;

    k_phase1<<<160, 256>>>(edge_index, roi, w1, b1, bn1g, bn1b, bn1m, bn1v,
                           bbox, dirs, prio, we1, be1);
    k_phase2<<<1152, 256>>>(we2, be2, wei, bei,
                            w2, b2, bn2g, bn2b, bn2m, bn2v,
                            w3, b3, wn, bnc);
    k_phase3<<<1024, 256>>>(out);
}

// round 6
// speedup vs baseline: 1.7155x; 1.1490x over previous
#include <cuda_runtime.h>
#include <cstdint>

// ---------------------------------------------------------------------------
// GroundingNet  B=16 N=64 E=512 — 2-launch, full-occupancy design
//  L1 (k_main, 1104 blocks x 256):
//    [0..63]     node path fully fused per 16 rows (512->256->128->64->8)
//    [64..79]    see/cnt build
//    [80..1103]  edge path per (b,i): in-block layer1 decomp + GEMM1 + GEMM3
//  L2 (k_out, 1024 blocks x 256): gather + write node_concepts + edge_concepts
//  (R5 fix: node smem stride 17 -> 20 so LDS.128/LDS.64 stay aligned)
// ---------------------------------------------------------------------------

#define DINL __device__ __forceinline__

constexpr int Bb = 16, Nn = 64, Ee = 512;
constexpr int CIMG = 512, H1c = 256, H2c = 128, H3c = 64;
constexpr int ROWS = Bb * Nn;             // 1024
constexpr int NODE_OUT = ROWS * Nn * 8;   // 524288
constexpr int NS = 20;                    // node smem row stride (aligned, bcast reads)

__device__ float g_node[ROWS * 8];
__device__ float g_rel[Bb * 64 * 64 * 8];   // 2 MB (L2-resident)
__device__ int   g_see[Bb * 64 * 64];
__device__ int   g_cnt[Bb * 64];

DINL float2 ffma2(float2 a, float2 b, float2 c) {
    float2 d;
    asm("fma.rn.f32x2 %0, %1, %2, %3;"
        : "=l"(reinterpret_cast<unsigned long long&>(d))
        : "l"(reinterpret_cast<unsigned long long&>(a)),
          "l"(reinterpret_cast<unsigned long long&>(b)),
          "l"(reinterpret_cast<unsigned long long&>(c)));
    return d;
}
DINL float sigmoidf_(float x) { return 1.f / (1.f + __expf(-x)); }

// ===========================================================================
// L1 : all compute
// ===========================================================================
__global__ void __launch_bounds__(256) k_main(
    const int*   __restrict__ edge_index,
    const float* __restrict__ roi,
    const float* __restrict__ w1,  const float* __restrict__ b1,
    const float* __restrict__ bng, const float* __restrict__ bnb,
    const float* __restrict__ bnm, const float* __restrict__ bnv,
    const float* __restrict__ w2,  const float* __restrict__ b2,
    const float* __restrict__ bn2g, const float* __restrict__ bn2b,
    const float* __restrict__ bn2m, const float* __restrict__ bn2v,
    const float* __restrict__ w3,  const float* __restrict__ b3,
    const float* __restrict__ wn,  const float* __restrict__ bnc,
    const float* __restrict__ bbox, const float* __restrict__ dirs,
    const float* __restrict__ prio,
    const float* __restrict__ we1, const float* __restrict__ be1,
    const float* __restrict__ we2, const float* __restrict__ be2,
    const float* __restrict__ wei, const float* __restrict__ bei) {
    __shared__ alignas(16) union {
        struct {                       // edge role: 10248 floats = 41 KB
            float ws[64 * 64];         // we2 [k][c]
            float e1[64 * 68];         // [k][j]  (aliased later as e2 [j][c])
            float weis[512];
            float attr[64 * 9];        // [j][d]
            float w1B[9 * 64];         // [d][k]  (second half of we1)
            float ai[64], be2s[64], beis[8];
        } e;
        struct {                       // node role: 10240 floats = 40.96 KB
            float xs[64 * NS];         // [k][r] stride 20
            float h1T[256 * NS];       // [c][r]
            float h2T[128 * NS];
            float h3T[64 * NS];
        } n;
        struct { int ssrc[512]; int sdst[512]; int srow[4096]; } s;
    } u;
    const int blk = blockIdx.x, t = threadIdx.x;

    if (blk < 64) {
        // ================= node path: 16 rows, 4 fused layers =================
        const int r0 = blk * 16;
        // ---- layer1: 16r x 256c, thread = (cp: 2 cols) x (rg: 8 rows) ----
        {
            const int cp = t & 127, rg = t >> 7;
            float2 acc[8] = {{0,0},{0,0},{0,0},{0,0},{0,0},{0,0},{0,0},{0,0}};
            for (int kc = 0; kc < CIMG; kc += 64) {
                {
                    const int r = t >> 4, k4 = (t & 15) * 4;
                    float4 v = *(const float4*)&roi[(size_t)(r0 + r) * CIMG + kc + k4];
                    u.n.xs[(k4 + 0) * NS + r] = v.x;
                    u.n.xs[(k4 + 1) * NS + r] = v.y;
                    u.n.xs[(k4 + 2) * NS + r] = v.z;
                    u.n.xs[(k4 + 3) * NS + r] = v.w;
                }
                __syncthreads();
                #pragma unroll 8
                for (int k = 0; k < 64; k++) {
                    const float2 w = *(const float2*)&w1[(size_t)(kc + k) * H1c + cp * 2];
                    const float4 x0 = *(const float4*)&u.n.xs[k * NS + rg * 8];
                    const float4 x1 = *(const float4*)&u.n.xs[k * NS + rg * 8 + 4];
                    acc[0] = ffma2(make_float2(x0.x, x0.x), w, acc[0]);
                    acc[1] = ffma2(make_float2(x0.y, x0.y), w, acc[1]);
                    acc[2] = ffma2(make_float2(x0.z, x0.z), w, acc[2]);
                    acc[3] = ffma2(make_float2(x0.w, x0.w), w, acc[3]);
                    acc[4] = ffma2(make_float2(x1.x, x1.x), w, acc[4]);
                    acc[5] = ffma2(make_float2(x1.y, x1.y), w, acc[5]);
                    acc[6] = ffma2(make_float2(x1.z, x1.z), w, acc[6]);
                    acc[7] = ffma2(make_float2(x1.w, x1.w), w, acc[7]);
                }
                __syncthreads();
            }
            const int c = cp * 2;
            const float s0 = bng[c]     * rsqrtf(bnv[c]     + 1e-5f);
            const float s1 = bng[c + 1] * rsqrtf(bnv[c + 1] + 1e-5f);
            const float h0 = bnb[c]     - bnm[c]     * s0;
            const float h1v = bnb[c + 1] - bnm[c + 1] * s1;
            const float q0 = b1[c], q1 = b1[c + 1];
            #pragma unroll
            for (int q = 0; q < 8; q++) {
                const int r = rg * 8 + q;
                u.n.h1T[(c    ) * NS + r] = fmaxf((acc[q].x + q0) * s0 + h0,  0.f);
                u.n.h1T[(c + 1) * NS + r] = fmaxf((acc[q].y + q1) * s1 + h1v, 0.f);
            }
        }
        __syncthreads();
        // ---- layer2: 16r x 128c, thread = (cp: 2 cols) x (rg: 4 rows) ----
        {
            const int cp = t & 63, rg = t >> 6;
            float2 acc[4] = {{0,0},{0,0},{0,0},{0,0}};
            #pragma unroll 8
            for (int k = 0; k < H1c; k++) {
                const float2 w = *(const float2*)&w2[(size_t)k * H2c + cp * 2];
                const float4 x = *(const float4*)&u.n.h1T[k * NS + rg * 4];
                acc[0] = ffma2(make_float2(x.x, x.x), w, acc[0]);
                acc[1] = ffma2(make_float2(x.y, x.y), w, acc[1]);
                acc[2] = ffma2(make_float2(x.z, x.z), w, acc[2]);
                acc[3] = ffma2(make_float2(x.w, x.w), w, acc[3]);
            }
            const int c = cp * 2;
            const float s0 = bn2g[c]     * rsqrtf(bn2v[c]     + 1e-5f);
            const float s1 = bn2g[c + 1] * rsqrtf(bn2v[c + 1] + 1e-5f);
            const float h0 = bn2b[c]     - bn2m[c]     * s0;
            const float h1v = bn2b[c + 1] - bn2m[c + 1] * s1;
            const float q0 = b2[c], q1 = b2[c + 1];
            #pragma unroll
            for (int q = 0; q < 4; q++) {
                const int r = rg * 4 + q;
                u.n.h2T[(c    ) * NS + r] = fmaxf((acc[q].x + q0) * s0 + h0,  0.f);
                u.n.h2T[(c + 1) * NS + r] = fmaxf((acc[q].y + q1) * s1 + h1v, 0.f);
            }
        }
        __syncthreads();
        // ---- layer3: 16r x 64c, thread = (cp: 2 cols) x (rg: 2 rows) ----
        {
            const int cp = t & 31, rg = t >> 5;
            float2 acc[2] = {{0,0},{0,0}};
            #pragma unroll 8
            for (int k = 0; k < H2c; k++) {
                const float2 w = *(const float2*)&w3[(size_t)k * H3c + cp * 2];
                const float2 x = *(const float2*)&u.n.h2T[k * NS + rg * 2];
                acc[0] = ffma2(make_float2(x.x, x.x), w, acc[0]);
                acc[1] = ffma2(make_float2(x.y, x.y), w, acc[1]);
            }
            const int c = cp * 2;
            const float q0 = b3[c], q1 = b3[c + 1];
            u.n.h3T[(c    ) * NS + rg * 2    ] = fmaxf(acc[0].x + q0, 0.f);
            u.n.h3T[(c + 1) * NS + rg * 2    ] = fmaxf(acc[0].y + q1, 0.f);
            u.n.h3T[(c    ) * NS + rg * 2 + 1] = fmaxf(acc[1].x + q0, 0.f);
            u.n.h3T[(c + 1) * NS + rg * 2 + 1] = fmaxf(acc[1].y + q1, 0.f);
        }
        __syncthreads();
        // ---- head: 16r x 8u + sigmoid ----
        if (t < 128) {
            const int r = t >> 3, uu = t & 7;
            float a = __ldg(&bnc[uu]);
            #pragma unroll 8
            for (int k = 0; k < 64; k++) a += u.n.h3T[k * NS + r] * __ldg(&wn[k * 8 + uu]);
            g_node[(size_t)(r0 + r) * 8 + uu] = sigmoidf_(a);
        }
    } else if (blk < 80) {
        // ======================= see / cnt build =======================
        const int b = blk - 64;
        const int* ei = edge_index + (size_t)b * 2 * Ee;
        for (int e = t; e < Ee; e += 256) { u.s.ssrc[e] = ei[e]; u.s.sdst[e] = ei[Ee + e]; }
        for (int i = t; i < 4096; i += 256)
            u.s.srow[i] = ((i & 63) == 0) ? (i >> 6) : 0;
        __syncthreads();
        if (t < 64) {
            const int n = t;
            int p = 1;
            #pragma unroll 8
            for (int e = 0; e < Ee; e++) {
                if (u.s.sdst[e] == n) {
                    if (p < 64) u.s.srow[n * 64 + p] = u.s.ssrc[e];
                    p++;
                }
            }
            g_cnt[b * 64 + n] = min(p, 64);
        }
        __syncthreads();
        for (int i = t; i < 1024; i += 256)
            *(int4*)&g_see[b * 4096 + i * 4] = *(const int4*)&u.s.srow[i * 4];
    } else {
        // =================== edge path: one (b,i) per block ===================
        const int bi = blk - 80, b = bi >> 6, il = bi & 63;
        float* ws  = u.e.ws;
        float* e1s = u.e.e1;
        float* e2s = u.e.e1;   // alias
        for (int i = t; i < 1024; i += 256)
            *(float4*)&ws[i * 4] = *(const float4*)&we2[i * 4];
        for (int i = t; i < 512; i += 256) u.e.weis[i] = wei[i];
        for (int i = t; i < 576; i += 256) {
            const int j = i / 9, d = i - j * 9;
            u.e.attr[i] = (d < 4) ? bbox[(b * 64 + j) * 4 + d] * (1.f / 1024.f)
                        : (d < 8) ? dirs[(b * 64 + j) * 4 + d - 4]
                                  : prio[b * 64 + j];
        }
        for (int i = t; i < 576; i += 256) u.e.w1B[i] = we1[576 + i];  // rows 9..17
        if (t < 64) u.e.be2s[t] = be2[t];
        if (t < 8)  u.e.beis[t] = bei[t];
        __syncthreads();
        if (t < 64) {   // ai[k] for own i
            float a = be1[t];
            #pragma unroll
            for (int d = 0; d < 9; d++) a += u.e.attr[il * 9 + d] * __ldg(&we1[d * 64 + t]);
            u.e.ai[t] = a;
        }
        __syncthreads();
        // ---- e1[k][j] = relu(ai[k] + attr[j] . w1B[.][k]) ----
        {
            const int jj = t & 63, kg = t >> 6, k0 = kg * 16;
            float a[9];
            #pragma unroll
            for (int d = 0; d < 9; d++) a[d] = u.e.attr[jj * 9 + d];
            float acc[16];
            #pragma unroll
            for (int q = 0; q < 16; q++) acc[q] = 0.f;
            #pragma unroll
            for (int d = 0; d < 9; d++) {
                #pragma unroll
                for (int k4 = 0; k4 < 4; k4++) {
                    const float4 w = *(const float4*)&u.e.w1B[d * 64 + k0 + k4 * 4];
                    acc[k4 * 4 + 0] += a[d] * w.x;
                    acc[k4 * 4 + 1] += a[d] * w.y;
                    acc[k4 * 4 + 2] += a[d] * w.z;
                    acc[k4 * 4 + 3] += a[d] * w.w;
                }
            }
            #pragma unroll
            for (int q = 0; q < 16; q++)
                e1s[(k0 + q) * 68 + jj] = fmaxf(u.e.ai[k0 + q] + acc[q], 0.f);
        }
        __syncthreads();
        // ---- GEMM1: 64j x 64c, thread tile 4j x 4c ----
        const int tc = t & 15, tj = t >> 4;
        float2 a01[4] = {{0,0},{0,0},{0,0},{0,0}};
        float2 a23[4] = {{0,0},{0,0},{0,0},{0,0}};
        #pragma unroll 8
        for (int k = 0; k < 64; k++) {
            const float4 a = *(const float4*)&e1s[k * 68 + tj * 4];
            const float4 w = *(const float4*)&ws[k * 64 + tc * 4];
            const float wv[4] = {w.x, w.y, w.z, w.w};
            const float2 r01 = make_float2(a.x, a.y);
            const float2 r23 = make_float2(a.z, a.w);
            #pragma unroll
            for (int ci = 0; ci < 4; ci++) {
                const float2 wc = make_float2(wv[ci], wv[ci]);
                a01[ci] = ffma2(r01, wc, a01[ci]);
                a23[ci] = ffma2(r23, wc, a23[ci]);
            }
        }
        __syncthreads();
        #pragma unroll
        for (int ci = 0; ci < 4; ci++) {
            const int cc = tc * 4 + ci;
            const float bb = u.e.be2s[cc];
            e2s[(tj * 4 + 0) * 68 + cc] = fmaxf(a01[ci].x + bb, 0.f);
            e2s[(tj * 4 + 1) * 68 + cc] = fmaxf(a01[ci].y + bb, 0.f);
            e2s[(tj * 4 + 2) * 68 + cc] = fmaxf(a23[ci].x + bb, 0.f);
            e2s[(tj * 4 + 3) * 68 + cc] = fmaxf(a23[ci].y + bb, 0.f);
        }
        __syncthreads();
        // ---- layer3 + sigmoid ----
        const int jj = t >> 2, rp = t & 3;
        float2 a3 = make_float2(u.e.beis[rp * 2], u.e.beis[rp * 2 + 1]);
        #pragma unroll 8
        for (int k = 0; k < 64; k++) {
            const float v = e2s[jj * 68 + k];
            const float2 wv = *(const float2*)&u.e.weis[k * 8 + rp * 2];
            a3 = ffma2(make_float2(v, v), wv, a3);
        }
        *(float2*)&g_rel[(((size_t)bi) * 64 + jj) * 8 + rp * 2] =
            make_float2(sigmoidf_(a3.x), sigmoidf_(a3.y));
    }
}

// ===========================================================================
// L2 : outputs (DRAM-write bound)
// ===========================================================================
__global__ void __launch_bounds__(256) k_out(float* __restrict__ out) {
    const int bi = blockIdx.x, b = bi >> 6, t = threadIdx.x;
    __shared__ int   ssee[64];
    __shared__ float smk[64];
    if (t < 64) {
        ssee[t] = g_see[bi * 64 + t];
        smk[t]  = (t < g_cnt[bi]) ? 1.f : 0.f;
    }
    __syncthreads();
    if (t < 128) {  // node_concepts row
        const int j = t >> 1, q = t & 1;
        float4 v = *(const float4*)&g_node[((size_t)b * 64 + ssee[j]) * 8 + q * 4];
        const float m = smk[j];
        v.x *= m; v.y *= m; v.z *= m; v.w *= m;
        *(float4*)&out[(size_t)bi * 512 + j * 8 + q * 4] = v;
    }
    const float4* rel4 = (const float4*)g_rel;
    float4* out4 = (float4*)(out + NODE_OUT) + (size_t)bi * 8192;
    #pragma unroll 4
    for (int idx = t; idx < 4096; idx += 256) {
        const int j = idx >> 6, k = idx & 63;
        const float m = smk[j] * smk[k];
        const int ro = (b * 4096 + ssee[j] * 64 + ssee[k]) * 2;
        float4 r0 = rel4[ro], r1 = rel4[ro + 1];
        r0.x *= m; r0.y *= m; r0.z *= m; r0.w *= m;
        r1.x *= m; r1.y *= m; r1.z *= m; r1.w *= m;
        __stcs(&out4[idx * 2],     r0);
        __stcs(&out4[idx * 2 + 1], r1);
    }
}

// ===========================================================================
extern "C" void kernel_launch(void* const* d_in, const int* in_sizes, int n_in,
                              void* d_out, int out_size) {
    const float* roi  = (const float*)d_in[0];
    const float* bbox = (const float*)d_in[1];
    const float* dirs = (const float*)d_in[2];
    const float* prio = (const float*)d_in[3];
    const float* w1   = (const float*)d_in[4];
    const float* b1   = (const float*)d_in[5];
    const float* bn1g = (const float*)d_in[6];
    const float* bn1b = (const float*)d_in[7];
    const float* bn1m = (const float*)d_in[8];
    const float* bn1v = (const float*)d_in[9];
    const float* w2   = (const float*)d_in[10];
    const float* b2   = (const float*)d_in[11];
    const float* bn2g = (const float*)d_in[12];
    const float* bn2b = (const float*)d_in[13];
    const float* bn2m = (const float*)d_in[14];
    const float* bn2v = (const float*)d_in[15];
    const float* w3   = (const float*)d_in[16];
    const float* b3   = (const float*)d_in[17];
    const float* wn   = (const float*)d_in[18];
    const float* bnc  = (const float*)d_in[19];
    const float* we1  = (const float*)d_in[20];
    const float* be1  = (const float*)d_in[21];
    const float* we2  = (const float*)d_in[22];
    const float* be2  = (const float*)d_in[23];
    const float* wei  = (const float*)d_in[24];
    const float* bei  = (const float*)d_in[25];
    const int* edge_index = (const int*)d_in[26];
    float* out = (float*)d_out;

    k_main<<<1104, 256>>>(edge_index, roi,
                          w1, b1, bn1g, bn1b, bn1m, bn1v,
                          w2, b2, bn2g, bn2b, bn2m, bn2v,
                          w3, b3, wn, bnc,
                          bbox, dirs, prio,
                          we1, be1, we2, be2, wei, bei);
    k_out<<<1024, 256>>>(out);
}